// round 14
// baseline (speedup 1.0000x reference)
#include <cuda_runtime.h>
#include <math.h>
#include <stdint.h>

// Problem constants
#define BT    8192     // B*T
#define TSEQ  512
#define NHQ   8
#define NKVH  4
#define DH    128

// Scratch (device globals: allocation-free contract)
__device__ float    g_QKV [BT * 2048];       // Q|K|V per row (fp32)
__device__ uint32_t g_hst [BT * 1024];       // tf32(hidden_states)
__device__ uint32_t g_AOt [BT * 1024];       // tf32(attention out)
__device__ uint32_t g_WtQKV[2048 * 1024];    // [WqT;WkT;WvT] [N][K] tf32 bits
__device__ uint32_t g_WtO [1024 * 1024];     // WoT
__device__ float    g_cos [TSEQ * 64];
__device__ float    g_sin [TSEQ * 64];

__device__ __forceinline__ uint32_t smem_u32(const void* p) {
    uint32_t r;
    asm("{ .reg .u64 t; cvta.to.shared.u64 t, %1; cvt.u32.u64 %0, t; }"
        : "=r"(r) : "l"(p));
    return r;
}
__device__ __forceinline__ uint32_t f2tf32(float f) {
    uint32_t r;
    asm("cvt.rna.tf32.f32 %0, %1;" : "=r"(r) : "f"(f));
    return r;
}
__device__ __forceinline__ void mma_tf32(float* c, const uint32_t* a,
                                         uint32_t b0, uint32_t b1) {
    asm volatile(
        "mma.sync.aligned.m16n8k8.row.col.f32.tf32.tf32.f32 "
        "{%0,%1,%2,%3}, {%4,%5,%6,%7}, {%8,%9}, {%0,%1,%2,%3};"
        : "+f"(c[0]), "+f"(c[1]), "+f"(c[2]), "+f"(c[3])
        : "r"(a[0]), "r"(a[1]), "r"(a[2]), "r"(a[3]), "r"(b0), "r"(b1));
}
__device__ __forceinline__ void cp16(uint32_t saddr, const void* gaddr) {
    asm volatile("cp.async.cg.shared.global [%0], [%1], 16;"
                 :: "r"(saddr), "l"(gaddr) : "memory");
}

// ---------------------------------------------------------------------------
// fp32 -> tf32 bits (RNA), vectorized
// ---------------------------------------------------------------------------
__global__ void to_tf32(const float* __restrict__ X, uint32_t* __restrict__ Y, int n4) {
    int i = blockIdx.x * blockDim.x + threadIdx.x;
    if (i >= n4) return;
    float4 v = reinterpret_cast<const float4*>(X)[i];
    uint4 r;
    r.x = f2tf32(v.x); r.y = f2tf32(v.y);
    r.z = f2tf32(v.z); r.w = f2tf32(v.w);
    reinterpret_cast<uint4*>(Y)[i] = r;
}

// ---------------------------------------------------------------------------
// RoPE cos/sin table: [tpos][i], i<64
// ---------------------------------------------------------------------------
__global__ void rope_table() {
    int tpos = blockIdx.x;
    int i    = threadIdx.x;
    float inv = powf(10000.0f, -(float)i * (1.0f / 64.0f));
    float s, c;
    sincosf((float)tpos * inv, &s, &c);
    g_cos[tpos * 64 + i] = c;
    g_sin[tpos * 64 + i] = s;
}

// ---------------------------------------------------------------------------
// All four weight transposes in ONE launch (z selects matrix).
// W[K=1024,N] fp32 -> Wt[N,K] tf32 bits.
// ---------------------------------------------------------------------------
__global__ void transpose_all(const float* __restrict__ Wq, const float* __restrict__ Wk,
                              const float* __restrict__ Wv, const float* __restrict__ Wo,
                              uint32_t* __restrict__ WtQKV, uint32_t* __restrict__ WtO) {
    const int z = blockIdx.z;
    const float* W;
    uint32_t* Wt;
    int N;
    if (z == 0)      { W = Wq; Wt = WtQKV;              N = 1024; }
    else if (z == 1) { W = Wk; Wt = WtQKV + 1024 * 1024; N = 512; }
    else if (z == 2) { W = Wv; Wt = WtQKV + 1536 * 1024; N = 512; }
    else             { W = Wo; Wt = WtO;                N = 1024; }
    const int K = 1024;
    int bx = blockIdx.x * 32;
    if (bx >= N) return;
    int by = blockIdx.y * 32;

    __shared__ float tile[32][33];
    int tx = threadIdx.x, ty = threadIdx.y;
#pragma unroll
    for (int i = 0; i < 32; i += 8)
        tile[ty + i][tx] = W[(size_t)(by + ty + i) * N + bx + tx];
    __syncthreads();
#pragma unroll
    for (int i = 0; i < 32; i += 8)
        Wt[(size_t)(bx + ty + i) * K + by + tx] = f2tf32(tile[tx][ty + i]);
}

// ---------------------------------------------------------------------------
// tf32 mma.sync GEMM, cp.async 3-stage pipeline + ks-level register double
// buffering of fragments. CTA tile 256x128, BK=32, 256 threads, 8 warps in
// 4(M) x 2(N), warp tile 64x64.
// ---------------------------------------------------------------------------
#define LDSS 36
#define GSTAGE 3
#define A_STAGE_WORDS (256 * LDSS)
#define B_STAGE_WORDS (128 * LDSS)
#define GEMM_SMEM_BYTES (GSTAGE * (A_STAGE_WORDS + B_STAGE_WORDS) * 4)   // 165888

__global__ __launch_bounds__(256) void tf32_gemm(const uint32_t* __restrict__ A,
                                                 const uint32_t* __restrict__ Bt,
                                                 float* __restrict__ C,
                                                 int N, int K) {
    extern __shared__ uint32_t gsm[];
    uint32_t* As = gsm;                                   // [GSTAGE][256*36]
    uint32_t* Bs = gsm + GSTAGE * A_STAGE_WORDS;          // [GSTAGE][128*36]

    const int t    = threadIdx.x;
    const int lane = t & 31;
    const int wid  = t >> 5;
    const int warp_m = wid & 3;     // rows warp_m*64
    const int warp_n = wid >> 2;    // cols warp_n*64
    const int row0 = blockIdx.y * 256;
    const int col0 = blockIdx.x * 128;
    const int r_ = t >> 3;      // 0..31
    const int c4 = t & 7;       // 16B chunk within 32-word K tile
    const int g = lane >> 2, c = lane & 3;
    const int nkt = K >> 5;

    float acc[4][8][4];
#pragma unroll
    for (int mi = 0; mi < 4; mi++)
#pragma unroll
        for (int ni = 0; ni < 8; ni++)
#pragma unroll
            for (int x = 0; x < 4; x++) acc[mi][ni][x] = 0.f;

    auto ISSUE = [&](int kt) {
        if (kt < nkt) {
            int s = kt % GSTAGE;
            uint32_t* as = As + s * A_STAGE_WORDS;
            uint32_t* bs = Bs + s * B_STAGE_WORDS;
#pragma unroll
            for (int j = 0; j < 8; j++) {
                int r = r_ + j * 32;
                cp16(smem_u32(&as[r * LDSS + c4 * 4]),
                     &A[(size_t)(row0 + r) * K + kt * 32 + c4 * 4]);
            }
#pragma unroll
            for (int j = 0; j < 4; j++) {
                int r = r_ + j * 32;
                cp16(smem_u32(&bs[r * LDSS + c4 * 4]),
                     &Bt[(size_t)(col0 + r) * K + kt * 32 + c4 * 4]);
            }
        }
        asm volatile("cp.async.commit_group;" ::: "memory");
    };

    uint32_t afr[2][4][4];
    uint32_t bfr[2][8][2];

    auto LDFRAG = [&](const uint32_t* as, const uint32_t* bs, int ks, int buf) {
        const int kc = ks * 8;
#pragma unroll
        for (int mi = 0; mi < 4; mi++) {
            int rb = warp_m * 64 + mi * 16 + g;
            afr[buf][mi][0] = as[rb * LDSS + kc + c];
            afr[buf][mi][1] = as[(rb + 8) * LDSS + kc + c];
            afr[buf][mi][2] = as[rb * LDSS + kc + 4 + c];
            afr[buf][mi][3] = as[(rb + 8) * LDSS + kc + 4 + c];
        }
#pragma unroll
        for (int ni = 0; ni < 8; ni++) {
            int cb = (warp_n * 64 + ni * 8 + g) * LDSS + kc + c;
            bfr[buf][ni][0] = bs[cb];
            bfr[buf][ni][1] = bs[cb + 4];
        }
    };

    ISSUE(0);
    ISSUE(1);
    for (int kt = 0; kt < nkt; kt++) {
        asm volatile("cp.async.wait_group 1;" ::: "memory");
        __syncthreads();
        ISSUE(kt + 2);   // buffer (kt-1)%3: consumed at kt-1, freed by barrier

        const uint32_t* as = As + (kt % GSTAGE) * A_STAGE_WORDS;
        const uint32_t* bs = Bs + (kt % GSTAGE) * B_STAGE_WORDS;
        LDFRAG(as, bs, 0, 0);
#pragma unroll
        for (int ks = 0; ks < 4; ks++) {
            const int cur = ks & 1;
            if (ks < 3) LDFRAG(as, bs, ks + 1, cur ^ 1);   // overlaps mmas below
#pragma unroll
            for (int ni = 0; ni < 8; ni++) {
                uint32_t b0 = bfr[cur][ni][0];
                uint32_t b1 = bfr[cur][ni][1];
#pragma unroll
                for (int mi = 0; mi < 4; mi++)
                    mma_tf32(acc[mi][ni], afr[cur][mi], b0, b1);
            }
        }
    }

#pragma unroll
    for (int mi = 0; mi < 4; mi++) {
        int rb = row0 + warp_m * 64 + mi * 16 + g;
#pragma unroll
        for (int ni = 0; ni < 8; ni++) {
            int cb = col0 + warp_n * 64 + ni * 8 + 2 * c;
            *reinterpret_cast<float2*>(&C[(size_t)rb * N + cb]) =
                make_float2(acc[mi][ni][0], acc[mi][ni][1]);
            *reinterpret_cast<float2*>(&C[(size_t)(rb + 8) * N + cb]) =
                make_float2(acc[mi][ni][2], acc[mi][ni][3]);
        }
    }
}

// ---------------------------------------------------------------------------
// Tensorized flash attention (tf32 mma.sync), causal, GQA, fused RoPE.
// QKV layout: row-major [BT][2048], Q at col h*128, K at 1024+kvh*128,
// V at 1536+kvh*128. Output written as tf32 bits to AOt.
// ---------------------------------------------------------------------------
#define QK_LDS 132
#define AP_LDS 68
#define ATTN2_SMEM_WORDS (128 * QK_LDS + 64 * QK_LDS + 16 * 64 * 8 + 128 * AP_LDS)
#define ATTN2_SMEM_BYTES (ATTN2_SMEM_WORDS * 4)

__global__ __launch_bounds__(256) void attn_mma(const float* __restrict__ QKV,
                                                uint32_t* __restrict__ AOt) {
    extern __shared__ uint32_t sm[];
    uint32_t* Qs = sm;                              // [128][132]
    uint32_t* Ks = Qs + 128 * QK_LDS;               // [64][132]
    uint32_t* Vs = Ks + 64 * QK_LDS;                // [16][64][8]
    uint32_t* Ps = Vs + 16 * 64 * 8;                // [128][68]

    const int t    = threadIdx.x;
    const int lane = t & 31;
    const int w    = t >> 5;
    const int qb   = 3 - blockIdx.x;                // heavy blocks first
    const int bh   = blockIdx.y;
    const int b    = bh >> 3;
    const int h    = bh & 7;
    const int kvh  = h >> 1;
    const int qrow0 = b * TSEQ + qb * 128;
    const int g = lane >> 2, c = lane & 3;
    const float scale = 0.08838834764831845f;

    // Load Q tile (128 rows x 128 d) with fused RoPE -> Qs (tf32)
#pragma unroll
    for (int j = 0; j < 8; j++) {
        int fid = j * 256 + t;
        int r   = fid >> 4;            // 0..127
        int hc  = (fid & 15) * 4;      // 0..60
        const float* qp = &QKV[(size_t)(qrow0 + r) * 2048 + h * 128 + hc];
        float4 x1 = *reinterpret_cast<const float4*>(qp);
        float4 x2 = *reinterpret_cast<const float4*>(qp + 64);
        int tpos = qb * 128 + r;
        float4 cs = *reinterpret_cast<const float4*>(&g_cos[tpos * 64 + hc]);
        float4 sn = *reinterpret_cast<const float4*>(&g_sin[tpos * 64 + hc]);
        int base = r * QK_LDS + hc;
        Qs[base + 0]  = f2tf32(x1.x * cs.x - x2.x * sn.x);
        Qs[base + 1]  = f2tf32(x1.y * cs.y - x2.y * sn.y);
        Qs[base + 2]  = f2tf32(x1.z * cs.z - x2.z * sn.z);
        Qs[base + 3]  = f2tf32(x1.w * cs.w - x2.w * sn.w);
        Qs[base + 64] = f2tf32(x2.x * cs.x + x1.x * sn.x);
        Qs[base + 65] = f2tf32(x2.y * cs.y + x1.y * sn.y);
        Qs[base + 66] = f2tf32(x2.z * cs.z + x1.z * sn.z);
        Qs[base + 67] = f2tf32(x2.w * cs.w + x1.w * sn.w);
    }

    float o[16][4];
#pragma unroll
    for (int ni = 0; ni < 16; ni++)
#pragma unroll
        for (int x = 0; x < 4; x++) o[ni][x] = 0.f;
    float m_i[2] = {-1e30f, -1e30f};
    float l_i[2] = {0.f, 0.f};

    const int nkt = 2 * qb + 2;
    for (int kt = 0; kt < nkt; kt++) {
        __syncthreads();
        const int krow0 = b * TSEQ + kt * 64;
        // K tile (64 x 128) with fused RoPE
#pragma unroll
        for (int j = 0; j < 4; j++) {
            int fid = j * 256 + t;
            int r   = fid >> 4;            // 0..63
            int hc  = (fid & 15) * 4;
            const float* kp = &QKV[(size_t)(krow0 + r) * 2048 + 1024 + kvh * 128 + hc];
            float4 x1 = *reinterpret_cast<const float4*>(kp);
            float4 x2 = *reinterpret_cast<const float4*>(kp + 64);
            int tpos = kt * 64 + r;
            float4 cs = *reinterpret_cast<const float4*>(&g_cos[tpos * 64 + hc]);
            float4 sn = *reinterpret_cast<const float4*>(&g_sin[tpos * 64 + hc]);
            int base = r * QK_LDS + hc;
            Ks[base + 0]  = f2tf32(x1.x * cs.x - x2.x * sn.x);
            Ks[base + 1]  = f2tf32(x1.y * cs.y - x2.y * sn.y);
            Ks[base + 2]  = f2tf32(x1.z * cs.z - x2.z * sn.z);
            Ks[base + 3]  = f2tf32(x1.w * cs.w - x2.w * sn.w);
            Ks[base + 64] = f2tf32(x2.x * cs.x + x1.x * sn.x);
            Ks[base + 65] = f2tf32(x2.y * cs.y + x1.y * sn.y);
            Ks[base + 66] = f2tf32(x2.z * cs.z + x1.z * sn.z);
            Ks[base + 67] = f2tf32(x2.w * cs.w + x1.w * sn.w);
        }
        // V tile (64 x 128), plain
#pragma unroll
        for (int j = 0; j < 8; j++) {
            int fid = j * 256 + t;
            int r   = fid >> 5;            // 0..63
            int d0  = (fid & 31) * 4;
            float4 vv = *reinterpret_cast<const float4*>(
                &QKV[(size_t)(krow0 + r) * 2048 + 1536 + kvh * 128 + d0]);
            uint32_t* vp = &Vs[(d0 >> 3) * 512 + r * 8 + (d0 & 7)];
            vp[0] = f2tf32(vv.x);
            vp[1] = f2tf32(vv.y);
            vp[2] = f2tf32(vv.z);
            vp[3] = f2tf32(vv.w);
        }
        __syncthreads();

        // S = Q K^T
        float sacc[8][4];
#pragma unroll
        for (int ni = 0; ni < 8; ni++)
#pragma unroll
            for (int x = 0; x < 4; x++) sacc[ni][x] = 0.f;

#pragma unroll
        for (int ks = 0; ks < 16; ks++) {
            const int kc = ks * 8;
            uint32_t a[4];
            int abase = (w * 16 + g) * QK_LDS + kc + c;
            a[0] = Qs[abase];
            a[1] = Qs[abase + 8 * QK_LDS];
            a[2] = Qs[abase + 4];
            a[3] = Qs[abase + 8 * QK_LDS + 4];
#pragma unroll
            for (int ni = 0; ni < 8; ni++) {
                int bb = (ni * 8 + g) * QK_LDS + kc + c;
                mma_tf32(sacc[ni], a, Ks[bb], Ks[bb + 4]);
            }
        }

        // online softmax
        const int row0 = qb * 128 + w * 16 + g;
        const bool diag = (kt >= 2 * qb);
        float rmax0 = -1e30f, rmax1 = -1e30f;
#pragma unroll
        for (int ni = 0; ni < 8; ni++) {
#pragma unroll
            for (int x = 0; x < 4; x++) {
                float sv = sacc[ni][x] * scale;
                if (diag) {
                    int col = kt * 64 + ni * 8 + 2 * c + (x & 1);
                    int row = row0 + ((x >= 2) ? 8 : 0);
                    if (col > row) sv = -1e30f;
                }
                sacc[ni][x] = sv;
                if (x < 2) rmax0 = fmaxf(rmax0, sv);
                else       rmax1 = fmaxf(rmax1, sv);
            }
        }
#pragma unroll
        for (int off = 1; off < 4; off <<= 1) {
            rmax0 = fmaxf(rmax0, __shfl_xor_sync(0xffffffffu, rmax0, off));
            rmax1 = fmaxf(rmax1, __shfl_xor_sync(0xffffffffu, rmax1, off));
        }
        float mn0 = fmaxf(m_i[0], rmax0);
        float mn1 = fmaxf(m_i[1], rmax1);
        float corr0 = __expf(m_i[0] - mn0);
        float corr1 = __expf(m_i[1] - mn1);
        float rsum0 = 0.f, rsum1 = 0.f;
#pragma unroll
        for (int ni = 0; ni < 8; ni++) {
            float p0 = __expf(sacc[ni][0] - mn0);
            float p1 = __expf(sacc[ni][1] - mn0);
            float p2 = __expf(sacc[ni][2] - mn1);
            float p3 = __expf(sacc[ni][3] - mn1);
            sacc[ni][0] = p0; sacc[ni][1] = p1;
            sacc[ni][2] = p2; sacc[ni][3] = p3;
            rsum0 += p0 + p1;
            rsum1 += p2 + p3;
        }
#pragma unroll
        for (int off = 1; off < 4; off <<= 1) {
            rsum0 += __shfl_xor_sync(0xffffffffu, rsum0, off);
            rsum1 += __shfl_xor_sync(0xffffffffu, rsum1, off);
        }
        l_i[0] = l_i[0] * corr0 + rsum0;
        l_i[1] = l_i[1] * corr1 + rsum1;
        m_i[0] = mn0;
        m_i[1] = mn1;
#pragma unroll
        for (int ni = 0; ni < 16; ni++) {
            o[ni][0] *= corr0; o[ni][1] *= corr0;
            o[ni][2] *= corr1; o[ni][3] *= corr1;
        }

        // P -> smem (tf32), warp-private rows
#pragma unroll
        for (int ni = 0; ni < 8; ni++) {
            int p0 = (w * 16 + g) * AP_LDS + ni * 8 + 2 * c;
            Ps[p0]     = f2tf32(sacc[ni][0]);
            Ps[p0 + 1] = f2tf32(sacc[ni][1]);
            int p1 = p0 + 8 * AP_LDS;
            Ps[p1]     = f2tf32(sacc[ni][2]);
            Ps[p1 + 1] = f2tf32(sacc[ni][3]);
        }
        __syncwarp();

        // O += P V
#pragma unroll
        for (int kc2 = 0; kc2 < 8; kc2++) {
            const int koff = kc2 * 8;
            uint32_t a[4];
            int abase = (w * 16 + g) * AP_LDS + koff + c;
            a[0] = Ps[abase];
            a[1] = Ps[abase + 8 * AP_LDS];
            a[2] = Ps[abase + 4];
            a[3] = Ps[abase + 8 * AP_LDS + 4];
#pragma unroll
            for (int ni = 0; ni < 16; ni++) {
                int vb = ni * 512 + (koff + c) * 8 + g;
                mma_tf32(o[ni], a, Vs[vb], Vs[vb + 32]);
            }
        }
    }

    // epilogue: write tf32 bits for the Wo GEMM
    float inv0 = 1.0f / l_i[0];
    float inv1 = 1.0f / l_i[1];
    const int orow = qrow0 + w * 16 + g;
#pragma unroll
    for (int ni = 0; ni < 16; ni++) {
        int col = h * 128 + ni * 8 + 2 * c;
        uint2 v0, v1;
        v0.x = f2tf32(o[ni][0] * inv0);
        v0.y = f2tf32(o[ni][1] * inv0);
        v1.x = f2tf32(o[ni][2] * inv1);
        v1.y = f2tf32(o[ni][3] * inv1);
        *reinterpret_cast<uint2*>(&AOt[(size_t)orow * 1024 + col])       = v0;
        *reinterpret_cast<uint2*>(&AOt[(size_t)(orow + 8) * 1024 + col]) = v1;
    }
}

// ---------------------------------------------------------------------------
extern "C" void kernel_launch(void* const* d_in, const int* in_sizes, int n_in,
                              void* d_out, int out_size) {
    const float* hs = (const float*)d_in[0];
    const float* Wq = (const float*)d_in[1];
    const float* Wk = (const float*)d_in[2];
    const float* Wv = (const float*)d_in[3];
    const float* Wo = (const float*)d_in[4];
    float* out = (float*)d_out;

    float *QKVp;
    uint32_t *hst, *AOt, *WtQKV, *WtO;
    cudaGetSymbolAddress((void**)&QKVp,  g_QKV);
    cudaGetSymbolAddress((void**)&hst,   g_hst);
    cudaGetSymbolAddress((void**)&AOt,   g_AOt);
    cudaGetSymbolAddress((void**)&WtQKV, g_WtQKV);
    cudaGetSymbolAddress((void**)&WtO,   g_WtO);

    cudaFuncSetAttribute(attn_mma, cudaFuncAttributeMaxDynamicSharedMemorySize,
                         ATTN2_SMEM_BYTES);
    cudaFuncSetAttribute(tf32_gemm, cudaFuncAttributeMaxDynamicSharedMemorySize,
                         GEMM_SMEM_BYTES);

    // Prelude (3 launches)
    to_tf32<<<(BT * 1024 / 4 + 255) / 256, 256>>>(hs, hst, BT * 1024 / 4);
    rope_table<<<TSEQ, 64>>>();
    transpose_all<<<dim3(32, 32, 4), dim3(32, 8)>>>(Wq, Wk, Wv, Wo, WtQKV, WtO);

    // Fused QKV projection (one GEMM, N=2048, CTA tile 256x128)
    tf32_gemm<<<dim3(2048 / 128, BT / 256), 256, GEMM_SMEM_BYTES>>>(hst, WtQKV, QKVp, 2048, 1024);

    // Attention (tensorized, fused RoPE) -> tf32 bits
    attn_mma<<<dim3(TSEQ / 128, 16 * NHQ), 256, ATTN2_SMEM_BYTES>>>(QKVp, AOt);

    // Output projection
    tf32_gemm<<<dim3(1024 / 128, BT / 256), 256, GEMM_SMEM_BYTES>>>(AOt, WtO, out, 1024, 1024);
}

// round 16
// speedup vs baseline: 1.6688x; 1.6688x over previous
#include <cuda_runtime.h>
#include <cuda_fp16.h>
#include <math.h>
#include <stdint.h>

// Problem constants
#define BT    8192     // B*T
#define TSEQ  512
#define NHQ   8
#define NKVH  4
#define DH    128

// Scratch (device globals). All fp16 data packed as half2 in uint32 words.
__device__ float    g_QKV [BT * 2048];       // Q|K|V per row (fp32, GEMM out)
__device__ uint32_t g_hs2 [BT * 512];        // fp16x2(hidden_states) [BT][512w]
__device__ uint32_t g_AO2 [BT * 512];        // fp16x2(attn out)      [BT][512w]
__device__ uint32_t g_WtQKV[2048 * 512];     // [WqT;WkT;WvT] [N][Kw] fp16x2
__device__ uint32_t g_WtO [1024 * 512];      // WoT [1024][512w]
__device__ float    g_cos [TSEQ * 64];
__device__ float    g_sin [TSEQ * 64];

__device__ __forceinline__ uint32_t smem_u32(const void* p) {
    uint32_t r;
    asm("{ .reg .u64 t; cvta.to.shared.u64 t, %1; cvt.u32.u64 %0, t; }"
        : "=r"(r) : "l"(p));
    return r;
}
__device__ __forceinline__ uint32_t pack_h2(float a, float b) {
    __half2 h = __float22half2_rn(make_float2(a, b));
    uint32_t r;
    memcpy(&r, &h, 4);
    return r;
}
__device__ __forceinline__ void mma_f16(float* c, const uint32_t* a,
                                        uint32_t b0, uint32_t b1) {
    asm volatile(
        "mma.sync.aligned.m16n8k16.row.col.f32.f16.f16.f32 "
        "{%0,%1,%2,%3}, {%4,%5,%6,%7}, {%8,%9}, {%0,%1,%2,%3};"
        : "+f"(c[0]), "+f"(c[1]), "+f"(c[2]), "+f"(c[3])
        : "r"(a[0]), "r"(a[1]), "r"(a[2]), "r"(a[3]), "r"(b0), "r"(b1));
}
__device__ __forceinline__ void cp16(uint32_t saddr, const void* gaddr) {
    asm volatile("cp.async.cg.shared.global [%0], [%1], 16;"
                 :: "r"(saddr), "l"(gaddr) : "memory");
}

// ---------------------------------------------------------------------------
// fp32 -> packed fp16x2 (RN)
// ---------------------------------------------------------------------------
__global__ void to_fp16(const float* __restrict__ X, uint32_t* __restrict__ Y, int n4) {
    int i = blockIdx.x * blockDim.x + threadIdx.x;
    if (i >= n4) return;
    float4 v = reinterpret_cast<const float4*>(X)[i];
    uint2 r;
    r.x = pack_h2(v.x, v.y);
    r.y = pack_h2(v.z, v.w);
    reinterpret_cast<uint2*>(Y)[i] = r;
}

// ---------------------------------------------------------------------------
// RoPE cos/sin table: [tpos][i], i<64
// ---------------------------------------------------------------------------
__global__ void rope_table() {
    int tpos = blockIdx.x;
    int i    = threadIdx.x;
    float inv = powf(10000.0f, -(float)i * (1.0f / 64.0f));
    float s, c;
    sincosf((float)tpos * inv, &s, &c);
    g_cos[tpos * 64 + i] = c;
    g_sin[tpos * 64 + i] = s;
}

// ---------------------------------------------------------------------------
// All four weight transposes in ONE launch (z selects matrix).
// W[K=1024,N] fp32 -> Wt[N][Kw=512] fp16x2 words (K-pairs packed).
// ---------------------------------------------------------------------------
__global__ void transpose_all(const float* __restrict__ Wq, const float* __restrict__ Wk,
                              const float* __restrict__ Wv, const float* __restrict__ Wo,
                              uint32_t* __restrict__ WtQKV, uint32_t* __restrict__ WtO) {
    const int z = blockIdx.z;
    const float* W;
    uint32_t* Wt;
    int N;
    if (z == 0)      { W = Wq; Wt = WtQKV;             N = 1024; }
    else if (z == 1) { W = Wk; Wt = WtQKV + 1024 * 512; N = 512; }
    else if (z == 2) { W = Wv; Wt = WtQKV + 1536 * 512; N = 512; }
    else             { W = Wo; Wt = WtO;               N = 1024; }
    const int Kw = 512;
    int bx = blockIdx.x * 32;
    if (bx >= N) return;
    int by = blockIdx.y * 32;     // k base

    __shared__ float tile[32][33];   // [k_local][n_local]
    int tx = threadIdx.x, ty = threadIdx.y;
#pragma unroll
    for (int i = 0; i < 32; i += 8)
        tile[ty + i][tx] = W[(size_t)(by + ty + i) * N + bx + tx];
    __syncthreads();
    if (tx < 16) {
#pragma unroll
        for (int i = 0; i < 32; i += 8) {
            int nl = ty + i;
            Wt[(size_t)(bx + nl) * Kw + (by >> 1) + tx] =
                pack_h2(tile[2 * tx][nl], tile[2 * tx + 1][nl]);
        }
    }
}

// ---------------------------------------------------------------------------
// fp16 mma.sync GEMM (m16n8k16), cp.async 3-stage pipeline.
// C[M,N] = A[M,2*Kw] @ Bt^T, A/Bt packed fp16x2 [.,Kw] words, K-major.
// CTA tile 256x128, BK=32 words (64 k), 256 threads, 8 warps 4(M)x2(N),
// warp tile 64x64.
// ---------------------------------------------------------------------------
#define LDSS 36
#define GSTAGE 3
#define A_STAGE_WORDS (256 * LDSS)
#define B_STAGE_WORDS (128 * LDSS)
#define GEMM_SMEM_BYTES (GSTAGE * (A_STAGE_WORDS + B_STAGE_WORDS) * 4)   // 165888

__global__ __launch_bounds__(256) void f16_gemm(const uint32_t* __restrict__ A,
                                                const uint32_t* __restrict__ Bt,
                                                float* __restrict__ C,
                                                int N, int Kw) {
    extern __shared__ uint32_t gsm[];
    uint32_t* As = gsm;                                   // [GSTAGE][256*36]
    uint32_t* Bs = gsm + GSTAGE * A_STAGE_WORDS;          // [GSTAGE][128*36]

    const int t    = threadIdx.x;
    const int lane = t & 31;
    const int wid  = t >> 5;
    const int warp_m = wid & 3;     // rows warp_m*64
    const int warp_n = wid >> 2;    // cols warp_n*64
    const int row0 = blockIdx.y * 256;
    const int col0 = blockIdx.x * 128;
    const int r_ = t >> 3;      // 0..31
    const int c4 = t & 7;       // 16B chunk within 32-word K tile
    const int g = lane >> 2, c = lane & 3;
    const int nkt = Kw >> 5;

    float acc[4][8][4];
#pragma unroll
    for (int mi = 0; mi < 4; mi++)
#pragma unroll
        for (int ni = 0; ni < 8; ni++)
#pragma unroll
            for (int x = 0; x < 4; x++) acc[mi][ni][x] = 0.f;

    auto ISSUE = [&](int kt) {
        if (kt < nkt) {
            int s = kt % GSTAGE;
            uint32_t* as = As + s * A_STAGE_WORDS;
            uint32_t* bs = Bs + s * B_STAGE_WORDS;
#pragma unroll
            for (int j = 0; j < 8; j++) {
                int r = r_ + j * 32;
                cp16(smem_u32(&as[r * LDSS + c4 * 4]),
                     &A[(size_t)(row0 + r) * Kw + kt * 32 + c4 * 4]);
            }
#pragma unroll
            for (int j = 0; j < 4; j++) {
                int r = r_ + j * 32;
                cp16(smem_u32(&bs[r * LDSS + c4 * 4]),
                     &Bt[(size_t)(col0 + r) * Kw + kt * 32 + c4 * 4]);
            }
        }
        asm volatile("cp.async.commit_group;" ::: "memory");
    };

    ISSUE(0);
    ISSUE(1);
    for (int kt = 0; kt < nkt; kt++) {
        asm volatile("cp.async.wait_group 1;" ::: "memory");
        __syncthreads();
        ISSUE(kt + 2);   // buffer (kt-1)%3: consumed at kt-1, freed by barrier

        const uint32_t* as = As + (kt % GSTAGE) * A_STAGE_WORDS;
        const uint32_t* bs = Bs + (kt % GSTAGE) * B_STAGE_WORDS;
#pragma unroll
        for (int ks = 0; ks < 4; ks++) {
            const int kc = ks * 8;
            uint32_t a[4][4];
#pragma unroll
            for (int mi = 0; mi < 4; mi++) {
                int rb = warp_m * 64 + mi * 16 + g;
                a[mi][0] = as[rb * LDSS + kc + c];
                a[mi][1] = as[(rb + 8) * LDSS + kc + c];
                a[mi][2] = as[rb * LDSS + kc + 4 + c];
                a[mi][3] = as[(rb + 8) * LDSS + kc + 4 + c];
            }
#pragma unroll
            for (int ni = 0; ni < 8; ni++) {
                int cb = (warp_n * 64 + ni * 8 + g) * LDSS + kc + c;
                uint32_t b0 = bs[cb];
                uint32_t b1 = bs[cb + 4];
#pragma unroll
                for (int mi = 0; mi < 4; mi++)
                    mma_f16(acc[mi][ni], a[mi], b0, b1);
            }
        }
    }

#pragma unroll
    for (int mi = 0; mi < 4; mi++) {
        int rb = row0 + warp_m * 64 + mi * 16 + g;
#pragma unroll
        for (int ni = 0; ni < 8; ni++) {
            int cb = col0 + warp_n * 64 + ni * 8 + 2 * c;
            *reinterpret_cast<float2*>(&C[(size_t)rb * N + cb]) =
                make_float2(acc[mi][ni][0], acc[mi][ni][1]);
            *reinterpret_cast<float2*>(&C[(size_t)(rb + 8) * N + cb]) =
                make_float2(acc[mi][ni][2], acc[mi][ni][3]);
        }
    }
}

// ---------------------------------------------------------------------------
// Tensorized flash attention (fp16 mma m16n8k16), causal, GQA, fused RoPE.
// QKV row-major [BT][2048] fp32: Q at h*128, K at 1024+kvh*128, V at 1536+.
// Smem (uint32 words): Qs[128][68] (64 d-words + pad), Ks[64][68],
// Vt[128][37] (d-major, key-pairs packed), Ps[128][36] (key-pair words).
// Output: packed fp16x2 words to AO2 [BT][512w].
// ---------------------------------------------------------------------------
#define QS_LDS 68
#define VT_LDS 37
#define PS_LDS 36
#define ATTN_SMEM_WORDS (128 * QS_LDS + 64 * QS_LDS + 128 * VT_LDS + 128 * PS_LDS)
#define ATTN_SMEM_BYTES (ATTN_SMEM_WORDS * 4)    // 89600

__global__ __launch_bounds__(256) void attn_mma(const float* __restrict__ QKV,
                                                uint32_t* __restrict__ AO2) {
    extern __shared__ uint32_t sm[];
    uint32_t* Qs = sm;                              // [128][68]
    uint32_t* Ks = Qs + 128 * QS_LDS;               // [64][68]
    uint32_t* Vt = Ks + 64 * QS_LDS;                // [128][37]
    uint32_t* Ps = Vt + 128 * VT_LDS;               // [128][36]
    __half*   Vth = reinterpret_cast<__half*>(Vt);  // halves, row stride 74

    const int t    = threadIdx.x;
    const int lane = t & 31;
    const int w    = t >> 5;
    const int qb   = 3 - blockIdx.x;                // heavy blocks first
    const int bh   = blockIdx.y;
    const int b    = bh >> 3;
    const int h    = bh & 7;
    const int kvh  = h >> 1;
    const int qrow0 = b * TSEQ + qb * 128;
    const int g = lane >> 2, c = lane & 3;
    const float scale = 0.08838834764831845f;

    // Load Q tile (128 rows x 128 d) with fused RoPE -> Qs (fp16x2 words)
#pragma unroll
    for (int j = 0; j < 8; j++) {
        int fid = j * 256 + t;
        int r   = fid >> 4;            // 0..127
        int hc  = (fid & 15) * 4;      // 0..60
        const float* qp = &QKV[(size_t)(qrow0 + r) * 2048 + h * 128 + hc];
        float4 x1 = *reinterpret_cast<const float4*>(qp);
        float4 x2 = *reinterpret_cast<const float4*>(qp + 64);
        int tpos = qb * 128 + r;
        float4 cs = *reinterpret_cast<const float4*>(&g_cos[tpos * 64 + hc]);
        float4 sn = *reinterpret_cast<const float4*>(&g_sin[tpos * 64 + hc]);
        int base = r * QS_LDS + (hc >> 1);
        Qs[base + 0]  = pack_h2(x1.x * cs.x - x2.x * sn.x, x1.y * cs.y - x2.y * sn.y);
        Qs[base + 1]  = pack_h2(x1.z * cs.z - x2.z * sn.z, x1.w * cs.w - x2.w * sn.w);
        Qs[base + 32] = pack_h2(x2.x * cs.x + x1.x * sn.x, x2.y * cs.y + x1.y * sn.y);
        Qs[base + 33] = pack_h2(x2.z * cs.z + x1.z * sn.z, x2.w * cs.w + x1.w * sn.w);
    }

    float o[16][4];
#pragma unroll
    for (int ni = 0; ni < 16; ni++)
#pragma unroll
        for (int x = 0; x < 4; x++) o[ni][x] = 0.f;
    float m_i[2] = {-1e30f, -1e30f};
    float l_i[2] = {0.f, 0.f};

    const int nkt = 2 * qb + 2;
    for (int kt = 0; kt < nkt; kt++) {
        __syncthreads();
        const int krow0 = b * TSEQ + kt * 64;
        // K tile (64 x 128) with fused RoPE -> Ks
#pragma unroll
        for (int j = 0; j < 4; j++) {
            int fid = j * 256 + t;
            int r   = fid >> 4;            // 0..63
            int hc  = (fid & 15) * 4;
            const float* kp = &QKV[(size_t)(krow0 + r) * 2048 + 1024 + kvh * 128 + hc];
            float4 x1 = *reinterpret_cast<const float4*>(kp);
            float4 x2 = *reinterpret_cast<const float4*>(kp + 64);
            int tpos = kt * 64 + r;
            float4 cs = *reinterpret_cast<const float4*>(&g_cos[tpos * 64 + hc]);
            float4 sn = *reinterpret_cast<const float4*>(&g_sin[tpos * 64 + hc]);
            int base = r * QS_LDS + (hc >> 1);
            Ks[base + 0]  = pack_h2(x1.x * cs.x - x2.x * sn.x, x1.y * cs.y - x2.y * sn.y);
            Ks[base + 1]  = pack_h2(x1.z * cs.z - x2.z * sn.z, x1.w * cs.w - x2.w * sn.w);
            Ks[base + 32] = pack_h2(x2.x * cs.x + x1.x * sn.x, x2.y * cs.y + x1.y * sn.y);
            Ks[base + 33] = pack_h2(x2.z * cs.z + x1.z * sn.z, x2.w * cs.w + x1.w * sn.w);
        }
        // V tile (64 x 128) -> Vt transposed (d-major, key minor)
#pragma unroll
        for (int j = 0; j < 8; j++) {
            int fid = j * 256 + t;
            int r   = fid >> 5;            // key 0..63
            int d0  = (fid & 31) * 4;
            float4 vv = *reinterpret_cast<const float4*>(
                &QKV[(size_t)(krow0 + r) * 2048 + 1536 + kvh * 128 + d0]);
            Vth[(d0 + 0) * 74 + r] = __float2half_rn(vv.x);
            Vth[(d0 + 1) * 74 + r] = __float2half_rn(vv.y);
            Vth[(d0 + 2) * 74 + r] = __float2half_rn(vv.z);
            Vth[(d0 + 3) * 74 + r] = __float2half_rn(vv.w);
        }
        __syncthreads();

        // S = Q K^T   (8 ks-steps of 16 k)
        float sacc[8][4];
#pragma unroll
        for (int ni = 0; ni < 8; ni++)
#pragma unroll
            for (int x = 0; x < 4; x++) sacc[ni][x] = 0.f;

#pragma unroll
        for (int ks = 0; ks < 8; ks++) {
            const int kc = ks * 8;
            uint32_t a[4];
            int abase = (w * 16 + g) * QS_LDS + kc + c;
            a[0] = Qs[abase];
            a[1] = Qs[abase + 8 * QS_LDS];
            a[2] = Qs[abase + 4];
            a[3] = Qs[abase + 8 * QS_LDS + 4];
#pragma unroll
            for (int ni = 0; ni < 8; ni++) {
                int bb = (ni * 8 + g) * QS_LDS + kc + c;
                mma_f16(sacc[ni], a, Ks[bb], Ks[bb + 4]);
            }
        }

        // online softmax
        const int row0 = qb * 128 + w * 16 + g;
        const bool diag = (kt >= 2 * qb);
        float rmax0 = -1e30f, rmax1 = -1e30f;
#pragma unroll
        for (int ni = 0; ni < 8; ni++) {
#pragma unroll
            for (int x = 0; x < 4; x++) {
                float sv = sacc[ni][x] * scale;
                if (diag) {
                    int col = kt * 64 + ni * 8 + 2 * c + (x & 1);
                    int row = row0 + ((x >= 2) ? 8 : 0);
                    if (col > row) sv = -1e30f;
                }
                sacc[ni][x] = sv;
                if (x < 2) rmax0 = fmaxf(rmax0, sv);
                else       rmax1 = fmaxf(rmax1, sv);
            }
        }
#pragma unroll
        for (int off = 1; off < 4; off <<= 1) {
            rmax0 = fmaxf(rmax0, __shfl_xor_sync(0xffffffffu, rmax0, off));
            rmax1 = fmaxf(rmax1, __shfl_xor_sync(0xffffffffu, rmax1, off));
        }
        float mn0 = fmaxf(m_i[0], rmax0);
        float mn1 = fmaxf(m_i[1], rmax1);
        float corr0 = __expf(m_i[0] - mn0);
        float corr1 = __expf(m_i[1] - mn1);
        float rsum0 = 0.f, rsum1 = 0.f;
#pragma unroll
        for (int ni = 0; ni < 8; ni++) {
            float p0 = __expf(sacc[ni][0] - mn0);
            float p1 = __expf(sacc[ni][1] - mn0);
            float p2 = __expf(sacc[ni][2] - mn1);
            float p3 = __expf(sacc[ni][3] - mn1);
            sacc[ni][0] = p0; sacc[ni][1] = p1;
            sacc[ni][2] = p2; sacc[ni][3] = p3;
            rsum0 += p0 + p1;
            rsum1 += p2 + p3;
        }
#pragma unroll
        for (int off = 1; off < 4; off <<= 1) {
            rsum0 += __shfl_xor_sync(0xffffffffu, rsum0, off);
            rsum1 += __shfl_xor_sync(0xffffffffu, rsum1, off);
        }
        l_i[0] = l_i[0] * corr0 + rsum0;
        l_i[1] = l_i[1] * corr1 + rsum1;
        m_i[0] = mn0;
        m_i[1] = mn1;
#pragma unroll
        for (int ni = 0; ni < 16; ni++) {
            o[ni][0] *= corr0; o[ni][1] *= corr0;
            o[ni][2] *= corr1; o[ni][3] *= corr1;
        }

        // P -> smem as packed fp16x2 (key pairs), warp-private rows
#pragma unroll
        for (int ni = 0; ni < 8; ni++) {
            Ps[(w * 16 + g) * PS_LDS + ni * 4 + c]     = pack_h2(sacc[ni][0], sacc[ni][1]);
            Ps[(w * 16 + g + 8) * PS_LDS + ni * 4 + c] = pack_h2(sacc[ni][2], sacc[ni][3]);
        }
        __syncwarp();

        // O += P V   (4 ks-steps of 16 keys)
#pragma unroll
        for (int ks = 0; ks < 4; ks++) {
            const int kc = ks * 8;
            uint32_t a[4];
            int abase = (w * 16 + g) * PS_LDS + kc + c;
            a[0] = Ps[abase];
            a[1] = Ps[abase + 8 * PS_LDS];
            a[2] = Ps[abase + 4];
            a[3] = Ps[abase + 8 * PS_LDS + 4];
#pragma unroll
            for (int ni = 0; ni < 16; ni++) {
                int vb = (ni * 8 + g) * VT_LDS + kc + c;
                mma_f16(o[ni], a, Vt[vb], Vt[vb + 4]);
            }
        }
    }

    // epilogue: write packed fp16x2 words for the Wo GEMM
    float inv0 = 1.0f / l_i[0];
    float inv1 = 1.0f / l_i[1];
    const int orow = qrow0 + w * 16 + g;
#pragma unroll
    for (int ni = 0; ni < 16; ni++) {
        int colw = h * 64 + ni * 4 + c;
        AO2[(size_t)orow * 512 + colw]       = pack_h2(o[ni][0] * inv0, o[ni][1] * inv0);
        AO2[(size_t)(orow + 8) * 512 + colw] = pack_h2(o[ni][2] * inv1, o[ni][3] * inv1);
    }
}

// ---------------------------------------------------------------------------
extern "C" void kernel_launch(void* const* d_in, const int* in_sizes, int n_in,
                              void* d_out, int out_size) {
    const float* hs = (const float*)d_in[0];
    const float* Wq = (const float*)d_in[1];
    const float* Wk = (const float*)d_in[2];
    const float* Wv = (const float*)d_in[3];
    const float* Wo = (const float*)d_in[4];
    float* out = (float*)d_out;

    float *QKVp;
    uint32_t *hs2, *AO2, *WtQKV, *WtO;
    cudaGetSymbolAddress((void**)&QKVp,  g_QKV);
    cudaGetSymbolAddress((void**)&hs2,   g_hs2);
    cudaGetSymbolAddress((void**)&AO2,   g_AO2);
    cudaGetSymbolAddress((void**)&WtQKV, g_WtQKV);
    cudaGetSymbolAddress((void**)&WtO,   g_WtO);

    cudaFuncSetAttribute(attn_mma, cudaFuncAttributeMaxDynamicSharedMemorySize,
                         ATTN_SMEM_BYTES);
    cudaFuncSetAttribute(f16_gemm, cudaFuncAttributeMaxDynamicSharedMemorySize,
                         GEMM_SMEM_BYTES);

    // Prelude (3 launches)
    to_fp16<<<(BT * 1024 / 4 + 255) / 256, 256>>>(hs, hs2, BT * 1024 / 4);
    rope_table<<<TSEQ, 64>>>();
    transpose_all<<<dim3(32, 32, 4), dim3(32, 8)>>>(Wq, Wk, Wv, Wo, WtQKV, WtO);

    // Fused QKV projection (one GEMM, N=2048, CTA tile 256x128)
    f16_gemm<<<dim3(2048 / 128, BT / 256), 256, GEMM_SMEM_BYTES>>>(hs2, WtQKV, QKVp, 2048, 512);

    // Attention (fp16 tensorized, fused RoPE) -> packed fp16
    attn_mma<<<dim3(TSEQ / 128, 16 * NHQ), 256, ATTN_SMEM_BYTES>>>(QKVp, AO2);

    // Output projection
    f16_gemm<<<dim3(1024 / 128, BT / 256), 256, GEMM_SMEM_BYTES>>>(AO2, WtO, out, 1024, 512);
}